// round 1
// baseline (speedup 1.0000x reference)
#include <cuda_runtime.h>
#include <cuda_bf16.h>

#define N_NODES 100000
#define E_EDGES 1600000
#define D 64

// Scratch: per-etype aggregation of raw x rows, plus degree counts.
__device__ float g_agg[3][N_NODES * D];   // 76.8 MB
__device__ float g_deg[3][N_NODES];       // 1.2 MB

// ---------------------------------------------------------------------------
// Zero the accumulators (d_out is fully written by out_kernel, no need there).
// ---------------------------------------------------------------------------
__global__ __launch_bounds__(256) void zero_kernel() {
    int idx = blockIdx.x * blockDim.x + threadIdx.x;
    int stride = gridDim.x * blockDim.x;
    float4* a = reinterpret_cast<float4*>(&g_agg[0][0]);
    const int na = 3 * N_NODES * D / 4;
    float4 z = make_float4(0.f, 0.f, 0.f, 0.f);
    for (int i = idx; i < na; i += stride) a[i] = z;
    float* dg = &g_deg[0][0];
    for (int i = idx; i < 3 * N_NODES; i += stride) dg[i] = 0.f;
}

// ---------------------------------------------------------------------------
// Edge phase: for each edge (per etype), scatter-add x[src] row (64 floats)
// into g_agg[e][dst] using vectorized red.global.add.v4.f32, and count degree.
// Half-warp (16 lanes) per edge: each lane moves one float4 (16 B).
// ---------------------------------------------------------------------------
__global__ __launch_bounds__(256) void edge_kernel(
    const float4* __restrict__ x4,
    const int* __restrict__ s0, const int* __restrict__ d0,
    const int* __restrict__ s1, const int* __restrict__ d1,
    const int* __restrict__ s2, const int* __restrict__ d2)
{
    int e = blockIdx.y;
    const int* __restrict__ src = (e == 0) ? s0 : (e == 1) ? s1 : s2;
    const int* __restrict__ dst = (e == 0) ? d0 : (e == 1) ? d1 : d2;
    float* agg = g_agg[e];
    float* deg = g_deg[e];

    int tid  = threadIdx.x;
    int warp = tid >> 5;
    int lane = tid & 31;
    int sub  = lane >> 4;   // which edge within the warp (0/1)
    int hl   = lane & 15;   // float4 slot within the 64-float row

    int wg = blockIdx.x * 8 + warp;          // global warp id
    int stride = gridDim.x * 16;             // edges per grid pass (8 warps * 2)

    for (int eid = wg * 2 + sub; eid < E_EDGES; eid += stride) {
        int s = __ldg(&src[eid]);
        int d = __ldg(&dst[eid]);
        float4 v = x4[s * 16 + hl];
        float* p = agg + d * 64 + hl * 4;
        asm volatile("red.global.add.v4.f32 [%0], {%1, %2, %3, %4};"
                     :: "l"(p), "f"(v.x), "f"(v.y), "f"(v.z), "f"(v.w)
                     : "memory");
        if (hl == 0) atomicAdd(deg + d, 1.0f);
    }
}

// ---------------------------------------------------------------------------
// Epilogue: out[n] = sum_e [deg_e(n)>0] * ( mean_e(n) @ W_e + b_e )
// Block processes 16-node tiles. Means (scaled by 1/deg, 3 etypes stacked ->
// K=192) staged transposed in shared so compute reads one broadcast LDS.128
// (4 nodes) + one coalesced LDS.32 (W) per 4 FMAs. W resident in shared for
// the whole (persistent) block.
// ---------------------------------------------------------------------------
__global__ __launch_bounds__(256) void out_kernel(
    const float* __restrict__ W0, const float* __restrict__ b0,
    const float* __restrict__ W1, const float* __restrict__ b1,
    const float* __restrict__ W2, const float* __restrict__ b2,
    float* __restrict__ out)
{
    extern __shared__ float sm[];
    float* Wsh = sm;              // 3 * 4096 = 12288 floats
    float* bsh = sm + 12288;      // 192 floats
    float* ash = sm + 12480;      // 192 rows x stride 20 = 3840 floats
    float* msk = sm + 16320;      // 3 * 16 = 48 floats

    int tid = threadIdx.x;

    for (int i = tid; i < 4096; i += 256) {
        Wsh[i]        = W0[i];
        Wsh[4096 + i] = W1[i];
        Wsh[8192 + i] = W2[i];
    }
    if (tid < 64) {
        bsh[tid]       = b0[tid];
        bsh[64 + tid]  = b1[tid];
        bsh[128 + tid] = b2[tid];
    }

    const int ntiles = (N_NODES + 15) / 16;
    int n  = tid >> 4;   // staging: node-in-tile 0..15
    int kq = tid & 15;   // staging: float4 chunk of the 64-float row
    int c  = tid & 63;   // compute: output column
    int g  = tid >> 6;   // compute: node group (4 nodes each), uniform per warp

    for (int tile = blockIdx.x; tile < ntiles; tile += gridDim.x) {
        __syncthreads();   // previous tile's compute done; also orders W load

        // ---- stage scaled means, transposed [k][node] ----
        int node = tile * 16 + n;
        #pragma unroll
        for (int e = 0; e < 3; e++) {
            float dv = 0.f;
            float4 v = make_float4(0.f, 0.f, 0.f, 0.f);
            if (node < N_NODES) {
                dv = g_deg[e][node];
                v  = reinterpret_cast<const float4*>(g_agg[e])[node * 16 + kq];
            }
            float inv = (dv > 0.f) ? (1.0f / dv) : 0.f;
            int kb = e * 64 + kq * 4;
            ash[(kb + 0) * 20 + n] = v.x * inv;
            ash[(kb + 1) * 20 + n] = v.y * inv;
            ash[(kb + 2) * 20 + n] = v.z * inv;
            ash[(kb + 3) * 20 + n] = v.w * inv;
            if (kq == 0) msk[e * 16 + n] = (dv > 0.f) ? 1.f : 0.f;
        }
        __syncthreads();

        // ---- compute: 4 nodes per thread, 1 column ----
        float acc0 = 0.f, acc1 = 0.f, acc2 = 0.f, acc3 = 0.f;
        #pragma unroll
        for (int e = 0; e < 3; e++) {
            const float* We = Wsh + e * 4096 + c;
            const float* ae = ash + e * 64 * 20 + g * 4;
            #pragma unroll 16
            for (int k = 0; k < 64; k++) {
                float4 av = *reinterpret_cast<const float4*>(ae + k * 20);
                float  w  = We[k * 64];
                acc0 += av.x * w;
                acc1 += av.y * w;
                acc2 += av.z * w;
                acc3 += av.w * w;
            }
        }

        // ---- bias (masked by deg>0) and writeback ----
        float accs[4] = {acc0, acc1, acc2, acc3};
        #pragma unroll
        for (int i = 0; i < 4; i++) {
            int nd = tile * 16 + g * 4 + i;
            if (nd < N_NODES) {
                float r = accs[i];
                #pragma unroll
                for (int e = 0; e < 3; e++)
                    r += msk[e * 16 + g * 4 + i] * bsh[e * 64 + c];
                out[nd * 64 + c] = r;
            }
        }
    }
}

// ---------------------------------------------------------------------------
// Inputs (metadata order): x, W0, b0, src0, dst0, W1, b1, src1, dst1,
//                          W2, b2, src2, dst2. Output: float32 [N, 64].
// ---------------------------------------------------------------------------
extern "C" void kernel_launch(void* const* d_in, const int* in_sizes, int n_in,
                              void* d_out, int out_size)
{
    const float* x  = (const float*)d_in[0];
    const float* W0 = (const float*)d_in[1];
    const float* b0 = (const float*)d_in[2];
    const int*   s0 = (const int*)  d_in[3];
    const int*   t0 = (const int*)  d_in[4];
    const float* W1 = (const float*)d_in[5];
    const float* b1 = (const float*)d_in[6];
    const int*   s1 = (const int*)  d_in[7];
    const int*   t1 = (const int*)  d_in[8];
    const float* W2 = (const float*)d_in[9];
    const float* b2 = (const float*)d_in[10];
    const int*   s2 = (const int*)  d_in[11];
    const int*   t2 = (const int*)  d_in[12];
    float* out = (float*)d_out;

    zero_kernel<<<1024, 256>>>();

    dim3 gE(1184, 3);
    edge_kernel<<<gE, 256>>>(reinterpret_cast<const float4*>(x),
                             s0, t0, s1, t1, s2, t2);

    cudaFuncSetAttribute(out_kernel,
                         cudaFuncAttributeMaxDynamicSharedMemorySize, 66000);
    out_kernel<<<592, 256, 16368 * sizeof(float)>>>(W0, b0, W1, b1, W2, b2, out);
}

// round 2
// speedup vs baseline: 1.0519x; 1.0519x over previous
#include <cuda_runtime.h>
#include <cuda_bf16.h>

#define N_NODES 100000
#define E_EDGES 1600000
#define D 64
#define NBLK 98                    // ceil(N_NODES / 1024)

// CSR scratch
__device__ int g_hist[3][N_NODES];        // per-etype in-degree
__device__ int g_scan[3][N_NODES];        // block-local inclusive scan
__device__ int g_bsum[3][NBLK];           // per-block totals
__device__ int g_bbase[3][NBLK];          // exclusive base per block
__device__ int g_cursor[3][N_NODES];      // start -> (after scatter) end
__device__ int g_bucket[3][E_EDGES];      // src ids grouped by dst

// ---------------------------------------------------------------------------
__global__ __launch_bounds__(256) void k_zero_hist() {
    int idx = blockIdx.x * blockDim.x + threadIdx.x;
    int stride = gridDim.x * blockDim.x;
    int4* h = reinterpret_cast<int4*>(&g_hist[0][0]);
    const int n4 = 3 * N_NODES / 4;
    int4 z = make_int4(0, 0, 0, 0);
    for (int i = idx; i < n4; i += stride) h[i] = z;
}

// ---------------------------------------------------------------------------
__global__ __launch_bounds__(256) void k_hist(
    const int* __restrict__ d0, const int* __restrict__ d1,
    const int* __restrict__ d2)
{
    int e = blockIdx.y;
    const int* __restrict__ dst = (e == 0) ? d0 : (e == 1) ? d1 : d2;
    int* hist = g_hist[e];
    int idx = blockIdx.x * blockDim.x + threadIdx.x;
    int stride = gridDim.x * blockDim.x;
    for (int i = idx; i < E_EDGES; i += stride)
        atomicAdd(hist + __ldg(&dst[i]), 1);
}

// ---------------------------------------------------------------------------
// Block-level inclusive scan of 1024 counts; emit block totals.
__global__ __launch_bounds__(1024) void k_blockscan() {
    __shared__ int wsum[32];
    int e = blockIdx.y;
    int n = blockIdx.x * 1024 + threadIdx.x;
    int lane = threadIdx.x & 31;
    int wid  = threadIdx.x >> 5;

    int v = (n < N_NODES) ? g_hist[e][n] : 0;
    int sc = v;
    #pragma unroll
    for (int d = 1; d < 32; d <<= 1) {
        int t = __shfl_up_sync(0xffffffffu, sc, d);
        if (lane >= d) sc += t;
    }
    if (lane == 31) wsum[wid] = sc;
    __syncthreads();
    if (wid == 0) {
        int s = wsum[lane];
        #pragma unroll
        for (int d = 1; d < 32; d <<= 1) {
            int t = __shfl_up_sync(0xffffffffu, s, d);
            if (lane >= d) s += t;
        }
        wsum[lane] = s;
    }
    __syncthreads();
    int inc = sc + (wid > 0 ? wsum[wid - 1] : 0);
    if (n < N_NODES) g_scan[e][n] = inc;
    if (threadIdx.x == 1023) g_bsum[e][blockIdx.x] = inc;
}

// Scan the NBLK block totals (tiny) -> exclusive bases.
__global__ void k_scansums() {
    int e = blockIdx.x;
    if (threadIdx.x == 0) {
        int acc = 0;
        for (int b = 0; b < NBLK; b++) {
            g_bbase[e][b] = acc;
            acc += g_bsum[e][b];
        }
    }
}

// cursor[n] = exclusive start offset of node n's bucket.
__global__ __launch_bounds__(256) void k_addback() {
    int e = blockIdx.y;
    int n = blockIdx.x * blockDim.x + threadIdx.x;
    if (n < N_NODES)
        g_cursor[e][n] = g_scan[e][n] - g_hist[e][n] + g_bbase[e][n >> 10];
}

// ---------------------------------------------------------------------------
__global__ __launch_bounds__(256) void k_scatter(
    const int* __restrict__ s0, const int* __restrict__ d0,
    const int* __restrict__ s1, const int* __restrict__ d1,
    const int* __restrict__ s2, const int* __restrict__ d2)
{
    int e = blockIdx.y;
    const int* __restrict__ src = (e == 0) ? s0 : (e == 1) ? s1 : s2;
    const int* __restrict__ dst = (e == 0) ? d0 : (e == 1) ? d1 : d2;
    int* cursor = g_cursor[e];
    int* bucket = g_bucket[e];
    int idx = blockIdx.x * blockDim.x + threadIdx.x;
    int stride = gridDim.x * blockDim.x;
    for (int i = idx; i < E_EDGES; i += stride) {
        int d = __ldg(&dst[i]);
        int pos = atomicAdd(cursor + d, 1);
        bucket[pos] = __ldg(&src[i]);
    }
}

// ---------------------------------------------------------------------------
// Fused gather + mean + GEMM + bias. One warp per node (grid-stride).
// After k_scatter, g_cursor[e][n] == end of node n's bucket; begin = end-cnt.
// ---------------------------------------------------------------------------
__global__ __launch_bounds__(256) void k_fused(
    const float* __restrict__ x,
    const float* __restrict__ W0, const float* __restrict__ b0,
    const float* __restrict__ W1, const float* __restrict__ b1,
    const float* __restrict__ W2, const float* __restrict__ b2,
    float* __restrict__ out)
{
    extern __shared__ float sm[];
    float* Wsh  = sm;                 // 3*4096
    float* bsh  = sm + 12288;         // 192
    float* mbuf = sm + 12480;         // 8 warps * 64

    int tid  = threadIdx.x;
    int lane = tid & 31;
    int wid  = tid >> 5;
    float* mb = mbuf + wid * 64;

    for (int i = tid; i < 4096; i += 256) {
        Wsh[i]        = W0[i];
        Wsh[4096 + i] = W1[i];
        Wsh[8192 + i] = W2[i];
    }
    if (tid < 64) {
        bsh[tid]       = b0[tid];
        bsh[64 + tid]  = b1[tid];
        bsh[128 + tid] = b2[tid];
    }
    __syncthreads();

    int gw = blockIdx.x * 8 + wid;
    int nwarps = gridDim.x * 8;
    int c = 2 * lane;

    for (int n = gw; n < N_NODES; n += nwarps) {
        float o0 = 0.f, o1 = 0.f;

        #pragma unroll
        for (int e = 0; e < 3; e++) {
            int end = g_cursor[e][n];
            int cnt = g_hist[e][n];
            if (cnt == 0) continue;
            int beg = end - cnt;
            const int* __restrict__ bucket = g_bucket[e];

            float a0 = 0.f, a1 = 0.f;
            int i = beg;
            // full chunks of 32 edges
            for (; i + 32 <= end; i += 32) {
                int myid = bucket[i + lane];
                #pragma unroll 8
                for (int j = 0; j < 32; j++) {
                    int s = __shfl_sync(0xffffffffu, myid, j);
                    float2 v = *reinterpret_cast<const float2*>(x + s * 64 + c);
                    a0 += v.x; a1 += v.y;
                }
            }
            // tail
            if (i < end) {
                int m = end - i;
                int myid = (i + lane < end) ? bucket[i + lane] : 0;
                for (int j = 0; j < m; j++) {
                    int s = __shfl_sync(0xffffffffu, myid, j);
                    float2 v = *reinterpret_cast<const float2*>(x + s * 64 + c);
                    a0 += v.x; a1 += v.y;
                }
            }

            float inv = 1.0f / (float)cnt;
            mb[c]     = a0 * inv;
            mb[c + 1] = a1 * inv;
            __syncwarp();

            const float* We = Wsh + e * 4096 + c;
            #pragma unroll 16
            for (int k = 0; k < 64; k++) {
                float mk = mb[k];
                float2 w = *reinterpret_cast<const float2*>(We + k * 64);
                o0 += mk * w.x;
                o1 += mk * w.y;
            }
            o0 += bsh[e * 64 + c];
            o1 += bsh[e * 64 + c + 1];
            __syncwarp();   // mbuf reuse
        }

        *reinterpret_cast<float2*>(out + n * 64 + c) = make_float2(o0, o1);
    }
}

// ---------------------------------------------------------------------------
extern "C" void kernel_launch(void* const* d_in, const int* in_sizes, int n_in,
                              void* d_out, int out_size)
{
    const float* x  = (const float*)d_in[0];
    const float* W0 = (const float*)d_in[1];
    const float* b0 = (const float*)d_in[2];
    const int*   s0 = (const int*)  d_in[3];
    const int*   t0 = (const int*)  d_in[4];
    const float* W1 = (const float*)d_in[5];
    const float* b1 = (const float*)d_in[6];
    const int*   s1 = (const int*)  d_in[7];
    const int*   t1 = (const int*)  d_in[8];
    const float* W2 = (const float*)d_in[9];
    const float* b2 = (const float*)d_in[10];
    const int*   s2 = (const int*)  d_in[11];
    const int*   t2 = (const int*)  d_in[12];
    float* out = (float*)d_out;

    k_zero_hist<<<256, 256>>>();

    dim3 gE(1184, 3);
    k_hist<<<gE, 256>>>(t0, t1, t2);

    dim3 gS(NBLK, 3);
    k_blockscan<<<gS, 1024>>>();
    k_scansums<<<3, 32>>>();

    dim3 gA((N_NODES + 255) / 256, 3);
    k_addback<<<gA, 256>>>();

    k_scatter<<<gE, 256>>>(s0, t0, s1, t1, s2, t2);

    cudaFuncSetAttribute(k_fused,
                         cudaFuncAttributeMaxDynamicSharedMemorySize, 53000);
    k_fused<<<1184, 256, 12992 * sizeof(float)>>>(x, W0, b0, W1, b1, W2, b2, out);
}